// round 16
// baseline (speedup 1.0000x reference)
#include <cuda_runtime.h>
#include <cuda_fp16.h>
#include <math_constants.h>
#include <cstdint>

// Problem constants: B=512, D=256, C=100000, m=4, lambda=1000
#define MAX_C 100000
#define MAX_B 512
#define DD    256

__device__ __half g_wh[(size_t)MAX_C * DD];   // fp16(normalized W)
__device__ __half g_xh[(size_t)MAX_B * DD];   // fp16(normalized X)
__device__ float  g_xlen[MAX_B];
__device__ int    g_flag[1024];               // per-stripe W-ready counters (0..4)

// ---------------------------------------------------------------------------
// Helpers
// ---------------------------------------------------------------------------
__device__ __forceinline__ uint32_t smem_u32(const void* p) {
    uint32_t a;
    asm("{ .reg .u64 t; cvta.to.shared.u64 t, %1; cvt.u32.u64 %0, t; }" : "=r"(a) : "l"(p));
    return a;
}
__device__ __forceinline__ void cp_async16(uint32_t dst, const void* src) {
    asm volatile("cp.async.cg.shared.global [%0], [%1], 16;" :: "r"(dst), "l"(src));
}
__device__ __forceinline__ void cp_commit() {
    asm volatile("cp.async.commit_group;" ::: "memory");
}
template <int N> __device__ __forceinline__ void cp_wait() {
    asm volatile("cp.async.wait_group %0;" :: "n"(N) : "memory");
}
__device__ __forceinline__ void ldsm_x4(uint32_t& r0, uint32_t& r1, uint32_t& r2, uint32_t& r3,
                                        uint32_t addr) {
    asm volatile("ldmatrix.sync.aligned.m8n8.x4.shared.b16 {%0,%1,%2,%3}, [%4];"
                 : "=r"(r0), "=r"(r1), "=r"(r2), "=r"(r3) : "r"(addr));
}
__device__ __forceinline__ void mma_16816(float& c0, float& c1, float& c2, float& c3,
                                          uint32_t a0, uint32_t a1, uint32_t a2, uint32_t a3,
                                          uint32_t b0, uint32_t b1) {
    asm volatile("mma.sync.aligned.m16n8k16.row.col.f32.f16.f16.f32 "
                 "{%0,%1,%2,%3}, {%4,%5,%6,%7}, {%8,%9}, {%0,%1,%2,%3};"
                 : "+f"(c0), "+f"(c1), "+f"(c2), "+f"(c3)
                 : "r"(a0), "r"(a1), "r"(a2), "r"(a3), "r"(b0), "r"(b1));
}
__device__ __forceinline__ void stcs_f2(float* p, float a, float b) {
    asm volatile("st.global.cs.v2.f32 [%0], {%1,%2};" :: "l"(p), "f"(a), "f"(b) : "memory");
}

// ---------------------------------------------------------------------------
// Reset + X prep: zero flags; normalize X rows -> fp16 (warp per row).
// ---------------------------------------------------------------------------
__global__ void reset_x_kernel(const float* __restrict__ X, int B) {
    int t = blockIdx.x * blockDim.x + threadIdx.x;
    for (int i = t; i < 1024; i += gridDim.x * blockDim.x) g_flag[i] = 0;

    int row  = t >> 5;
    int lane = t & 31;
    if (row >= B) return;
    const float* src = X + (size_t)row * DD;
    float4 v0 = *(const float4*)(src + lane * 4);
    float4 v1 = *(const float4*)(src + 128 + lane * 4);
    float s = v0.x*v0.x + v0.y*v0.y + v0.z*v0.z + v0.w*v0.w
            + v1.x*v1.x + v1.y*v1.y + v1.z*v1.z + v1.w*v1.w;
    #pragma unroll
    for (int o = 16; o; o >>= 1) s += __shfl_xor_sync(0xffffffffu, s, o);
    float inv = rsqrtf(s);
    if (lane == 0) g_xlen[row] = s * inv;
    __half* dst = g_xh + (size_t)row * DD;
    *(__half2*)(dst + lane * 4)           = __floats2half2_rn(v0.x * inv, v0.y * inv);
    *(__half2*)(dst + lane * 4 + 2)       = __floats2half2_rn(v0.z * inv, v0.w * inv);
    *(__half2*)(dst + 128 + lane * 4)     = __floats2half2_rn(v1.x * inv, v1.y * inv);
    *(__half2*)(dst + 128 + lane * 4 + 2) = __floats2half2_rn(v1.z * inv, v1.w * inv);
}

// ---------------------------------------------------------------------------
// Persistent fused GEMM. 296 CTAs (2/SM, one wave). CTA = (m = bid&3,
// slot = bid>>2). Slot walks stripes slot, slot+74, ...
// Each stripe's 128 W rows are prepped (fp32->fp16 normalize) by its 4
// m-CTAs (32 rows each, 4 rows/warp), with prep-ahead distance 2 tiles.
// GEMM per tile: R13 champion (A K-resident, B ring of 3, ks db, fast-path
// epilogue, streaming stores).
// ---------------------------------------------------------------------------
#define BM 128
#define BN 128
#define BK 64
#define NCHUNK 4
#define NSLOT  74
#define NCTA   296

#define A_OFF      0                     // 4 slabs of 16 KB = 65536
#define B_OFF      65536                 // ring 3 x 16 KB = 49152
#define SMEM_TOTAL 114688                // 112 KB -> 2 CTAs/SM

__global__ __launch_bounds__(256, 2)
void angle_mma_kernel(const float* __restrict__ W, const int* __restrict__ Y,
                      float* __restrict__ out, int C, int ntiles)
{
    extern __shared__ char smem[];
    const uint32_t sbase = smem_u32(smem);
    const int tid  = threadIdx.x;
    const int wid  = tid >> 5;
    const int lane = tid & 31;
    const int wm   = wid >> 2;     // 0..1 : warp m (64 rows)
    const int wn   = wid & 3;      // 0..3 : warp n (32 cols)

    const int m    = blockIdx.x & 3;
    const int slot = blockIdx.x >> 2;
    const int bm   = m * BM;
    const int T    = (ntiles - slot + NSLOT - 1) / NSLOT;   // tiles for this slot

    // ---- W stripe prep: this CTA's 32 rows (4 per warp), MLP-maximized ----
    auto prep_stripe = [&](int stripe) {
        const int rbase = stripe * BN + m * 32 + wid * 4;
        float4 v[4][2];
        bool ok[4];
        #pragma unroll
        for (int r = 0; r < 4; r++) {
            const int row = rbase + r;
            ok[r] = (row < C);
            const float* src = W + (size_t)(ok[r] ? row : 0) * DD;
            v[r][0] = *(const float4*)(src + lane * 4);
            v[r][1] = *(const float4*)(src + 128 + lane * 4);
        }
        float s[4];
        #pragma unroll
        for (int r = 0; r < 4; r++)
            s[r] = v[r][0].x*v[r][0].x + v[r][0].y*v[r][0].y + v[r][0].z*v[r][0].z + v[r][0].w*v[r][0].w
                 + v[r][1].x*v[r][1].x + v[r][1].y*v[r][1].y + v[r][1].z*v[r][1].z + v[r][1].w*v[r][1].w;
        #pragma unroll
        for (int o = 16; o; o >>= 1) {
            #pragma unroll
            for (int r = 0; r < 4; r++) s[r] += __shfl_xor_sync(0xffffffffu, s[r], o);
        }
        #pragma unroll
        for (int r = 0; r < 4; r++) {
            if (!ok[r]) continue;
            const float inv = rsqrtf(s[r]);
            __half* dst = g_wh + (size_t)(rbase + r) * DD;
            *(__half2*)(dst + lane * 4)           = __floats2half2_rn(v[r][0].x * inv, v[r][0].y * inv);
            *(__half2*)(dst + lane * 4 + 2)       = __floats2half2_rn(v[r][0].z * inv, v[r][0].w * inv);
            *(__half2*)(dst + 128 + lane * 4)     = __floats2half2_rn(v[r][1].x * inv, v[r][1].y * inv);
            *(__half2*)(dst + 128 + lane * 4 + 2) = __floats2half2_rn(v[r][1].z * inv, v[r][1].w * inv);
        }
        __threadfence();
        __syncthreads();
        if (tid == 0) atomicAdd(&g_flag[stripe], 1);
    };
    auto wait_stripe = [&](int stripe) {
        if (tid == 0) {
            while (atomicAdd(&g_flag[stripe], 0) < 4) __nanosleep(32);
            __threadfence();
        }
        __syncthreads();
    };

    // ---- loaders ----
    auto load_a_all = [&]() {       // 128 rows x 256 k, 4 slabs of 16 KB
        for (int i = 0; i < 16; i++) {
            int t2 = tid + i * 256;
            int chunk = t2 >> 10;
            int w3    = t2 & 1023;
            int row = w3 >> 3, blk = w3 & 7;
            uint32_t off = (uint32_t)(row * 128) + (uint32_t)((blk ^ (row & 7)) << 4);
            cp_async16(sbase + A_OFF + chunk * 16384 + off,
                       g_xh + (size_t)(bm + row) * DD + chunk * BK + blk * 8);
        }
    };
    auto load_b = [&](int buf, int kc, int bn) {  // 128 rows x 64 k
        const uint32_t bb = sbase + B_OFF + (uint32_t)buf * 16384;
        #pragma unroll
        for (int i = 0; i < 4; i++) {
            int g = tid + i * 256;
            int row = g >> 3, blk = g & 7;
            int rg = bn + row; if (rg >= C) rg = C - 1;
            uint32_t off = (uint32_t)(row * 128) + (uint32_t)((blk ^ (row & 7)) << 4);
            cp_async16(bb + off, g_wh + (size_t)rg * DD + kc + blk * 8);
        }
    };

    // ---- CTA prologue: A (async) + prep stripes t=0,1 ----
    load_a_all();
    cp_commit();                                   // group: A
    prep_stripe(slot);                             // t = 0
    if (T > 1) prep_stripe(slot + NSLOT);          // t = 1
    wait_stripe(slot);

    // fragment row bases (XOR-composable)
    const int a_hi = lane >> 4;
    uint32_t a_rel[4], b_rel[2];
    #pragma unroll
    for (int mt = 0; mt < 4; mt++) {
        int r = wm * 64 + mt * 16 + (lane & 15);
        a_rel[mt] = (uint32_t)(r * 128) + (uint32_t)((r & 7) << 4);
    }
    #pragma unroll
    for (int bt = 0; bt < 2; bt++) {
        int r = wn * 32 + bt * 16 + ((lane >> 3) & 1) * 8 + (lane & 7);
        b_rel[bt] = (uint32_t)(r * 128) + (uint32_t)((r & 7) << 4);
    }

    // per-CTA epilogue constants (hoisted out of tile loop)
    const float inv_pi     = 1.0f / CUDART_PI_F;
    const float inv_1plamb = 1.0f / 1001.0f;
    float xl[8]; int lab[8];
    #pragma unroll
    for (int mt = 0; mt < 4; mt++) {
        const int r0 = bm + wm * 64 + mt * 16 + (lane >> 2);
        xl[2 * mt]      = g_xlen[r0];
        xl[2 * mt + 1]  = g_xlen[r0 + 8];
        lab[2 * mt]     = Y[r0];
        lab[2 * mt + 1] = Y[r0 + 8];
    }

    // ---- persistent tile loop ----
    for (int t = 0; t < T; t++) {
        const int stripe = slot + t * NSLOT;
        const int bn     = stripe * BN;
        if (t > 0) wait_stripe(stripe);            // prepped at tile t-2 (or prologue)

        load_b(0, 0, bn);  cp_commit();
        load_b(1, BK, bn); cp_commit();

        float c[4][4][4];
        #pragma unroll
        for (int mt = 0; mt < 4; mt++)
            #pragma unroll
            for (int nt = 0; nt < 4; nt++)
                #pragma unroll
                for (int q = 0; q < 4; q++) c[mt][nt][q] = 0.f;

        #pragma unroll
        for (int ck = 0; ck < NCHUNK; ck++) {
            if (ck == NCHUNK - 1) cp_wait<0>(); else cp_wait<1>();
            __syncthreads();                       // B[ck%3] (+A on first tile) visible

            if (ck + 2 < NCHUNK) {
                load_b((ck + 2) % 3, (ck + 2) * BK, bn);
                cp_commit();
            }

            const uint32_t ab = sbase + A_OFF + (uint32_t)ck * 16384;
            const uint32_t bb = sbase + B_OFF + (uint32_t)(ck % 3) * 16384;

            uint32_t a[2][4][4], b[2][2][4];
            const uint32_t k0 = (uint32_t)(a_hi << 4);
            #pragma unroll
            for (int mt = 0; mt < 4; mt++)
                ldsm_x4(a[0][mt][0], a[0][mt][1], a[0][mt][2], a[0][mt][3],
                        ab + (a_rel[mt] ^ k0));
            #pragma unroll
            for (int bt = 0; bt < 2; bt++)
                ldsm_x4(b[0][bt][0], b[0][bt][1], b[0][bt][2], b[0][bt][3],
                        bb + (b_rel[bt] ^ k0));

            #pragma unroll
            for (int ks = 0; ks < 4; ks++) {
                const int cur = ks & 1, nxt = cur ^ 1;
                if (ks < 3) {
                    const uint32_t kc = (uint32_t)(((ks + 1) * 2 + a_hi) << 4);
                    #pragma unroll
                    for (int mt = 0; mt < 4; mt++)
                        ldsm_x4(a[nxt][mt][0], a[nxt][mt][1], a[nxt][mt][2], a[nxt][mt][3],
                                ab + (a_rel[mt] ^ kc));
                    #pragma unroll
                    for (int bt = 0; bt < 2; bt++)
                        ldsm_x4(b[nxt][bt][0], b[nxt][bt][1], b[nxt][bt][2], b[nxt][bt][3],
                                bb + (b_rel[bt] ^ kc));
                }
                #pragma unroll
                for (int mt = 0; mt < 4; mt++) {
                    #pragma unroll
                    for (int nt = 0; nt < 4; nt++) {
                        const int bt = nt >> 1, sub = nt & 1;
                        mma_16816(c[mt][nt][0], c[mt][nt][1], c[mt][nt][2], c[mt][nt][3],
                                  a[cur][mt][0], a[cur][mt][1], a[cur][mt][2], a[cur][mt][3],
                                  b[cur][bt][sub], b[cur][bt][2 + sub]);
                    }
                }
            }
        }

        // prep-ahead: stripe t+2 (frag regs dead here; epilogue hides latency)
        if (t + 2 < T) prep_stripe(slot + (t + 2) * NSLOT);

        // ---- epilogue for tile t ----
        #pragma unroll
        for (int mt = 0; mt < 4; mt++) {
            #pragma unroll
            for (int half = 0; half < 2; half++) {
                const int   rr  = bm + wm * 64 + mt * 16 + (lane >> 2) + half * 8;
                const float xlv = xl[2 * mt + half];
                const int   lbv = lab[2 * mt + half];
                float* rowp = out + (size_t)rr * C;
                const bool hit = ((unsigned)(lbv - bn) < (unsigned)BN);

                if (!hit) {
                    #pragma unroll
                    for (int nt = 0; nt < 4; nt++) {
                        const int col = bn + wn * 32 + nt * 8 + (lane & 3) * 2;
                        if (col >= C) continue;   // col even, C even -> col+1 valid
                        float v0 = c[mt][nt][half * 2 + 0];
                        float v1 = c[mt][nt][half * 2 + 1];
                        v0 = fminf(fmaxf(v0, -1.0f), 1.0f);
                        v1 = fminf(fmaxf(v1, -1.0f), 1.0f);
                        stcs_f2(rowp + col, v0 * xlv, v1 * xlv);
                    }
                } else {
                    #pragma unroll
                    for (int nt = 0; nt < 4; nt++) {
                        const int col = bn + wn * 32 + nt * 8 + (lane & 3) * 2;
                        if (col >= C) continue;
                        float v0 = c[mt][nt][half * 2 + 0];
                        float v1 = c[mt][nt][half * 2 + 1];
                        v0 = fminf(fmaxf(v0, -1.0f), 1.0f);
                        v1 = fminf(fmaxf(v1, -1.0f), 1.0f);
                        float f0 = v0 * xlv, f1 = v1 * xlv;
                        if (col == lbv || col + 1 == lbv) {
                            const bool second = (col + 1 == lbv);
                            float cv = second ? v1 : v0;
                            float c2   = cv * cv;
                            float cosm = 8.0f * c2 * c2 - 8.0f * c2 + 1.0f;
                            float kf   = floorf(4.0f * acosf(cv) * inv_pi);
                            float sign = 1.0f - 2.0f * fmodf(kf, 2.0f);
                            float phi  = sign * cosm - 2.0f * kf;
                            float fm   = second ? f1 : f0;
                            fm += (phi * xlv - fm) * inv_1plamb;
                            if (second) f1 = fm; else f0 = fm;
                        }
                        stcs_f2(rowp + col, f0, f1);
                    }
                }
            }
        }
    }
}

// ---------------------------------------------------------------------------
// Launch
// ---------------------------------------------------------------------------
extern "C" void kernel_launch(void* const* d_in, const int* in_sizes, int n_in,
                              void* d_out, int out_size)
{
    const float* x = (const float*)d_in[0];
    const float* w = (const float*)d_in[1];
    const int*   y = (const int*)d_in[2];
    float* out     = (float*)d_out;

    const int B = in_sizes[2];            // 512
    const int D = in_sizes[0] / B;        // 256
    const int C = in_sizes[1] / D;        // 100000
    (void)D;

    static bool attr_set = false;
    if (!attr_set) {
        cudaFuncSetAttribute(angle_mma_kernel,
                             cudaFuncAttributeMaxDynamicSharedMemorySize, SMEM_TOTAL);
        attr_set = true;
    }

    // reset flags + X prep
    reset_x_kernel<<<64, 256>>>(x, B);

    const int ntiles = (C + BN - 1) / BN;          // 782
    angle_mma_kernel<<<NCTA, 256, SMEM_TOTAL>>>(w, y, out, C, ntiles);
}

// round 17
// speedup vs baseline: 1.1233x; 1.1233x over previous
#include <cuda_runtime.h>
#include <cuda_fp16.h>
#include <math_constants.h>
#include <cstdint>

// Problem constants: B=512, D=256, C=100000, m=4, lambda=1000
#define MAX_C 100000
#define MAX_B 512
#define DD    256

__device__ __half g_wh[(size_t)MAX_C * DD];   // fp16(normalized W)
__device__ __half g_xh[(size_t)MAX_B * DD];   // fp16(normalized X)
__device__ float  g_xlen[MAX_B];

// ---------------------------------------------------------------------------
// Helpers
// ---------------------------------------------------------------------------
__device__ __forceinline__ uint32_t smem_u32(const void* p) {
    uint32_t a;
    asm("{ .reg .u64 t; cvta.to.shared.u64 t, %1; cvt.u32.u64 %0, t; }" : "=r"(a) : "l"(p));
    return a;
}
__device__ __forceinline__ void cp_async16(uint32_t dst, const void* src) {
    asm volatile("cp.async.cg.shared.global [%0], [%1], 16;" :: "r"(dst), "l"(src));
}
__device__ __forceinline__ void cp_commit() {
    asm volatile("cp.async.commit_group;" ::: "memory");
}
template <int N> __device__ __forceinline__ void cp_wait() {
    asm volatile("cp.async.wait_group %0;" :: "n"(N) : "memory");
}
__device__ __forceinline__ void ldsm_x4(uint32_t& r0, uint32_t& r1, uint32_t& r2, uint32_t& r3,
                                        uint32_t addr) {
    asm volatile("ldmatrix.sync.aligned.m8n8.x4.shared.b16 {%0,%1,%2,%3}, [%4];"
                 : "=r"(r0), "=r"(r1), "=r"(r2), "=r"(r3) : "r"(addr));
}
__device__ __forceinline__ void mma_16816(float& c0, float& c1, float& c2, float& c3,
                                          uint32_t a0, uint32_t a1, uint32_t a2, uint32_t a3,
                                          uint32_t b0, uint32_t b1) {
    asm volatile("mma.sync.aligned.m16n8k16.row.col.f32.f16.f16.f32 "
                 "{%0,%1,%2,%3}, {%4,%5,%6,%7}, {%8,%9}, {%0,%1,%2,%3};"
                 : "+f"(c0), "+f"(c1), "+f"(c2), "+f"(c3)
                 : "r"(a0), "r"(a1), "r"(a2), "r"(a3), "r"(b0), "r"(b1));
}
__device__ __forceinline__ void stcs_f2(float* p, float a, float b) {
    asm volatile("st.global.cs.v2.f32 [%0], {%1,%2};" :: "l"(p), "f"(a), "f"(b) : "memory");
}
// streaming (evict-first) float4 load: input is never re-read
__device__ __forceinline__ float4 ldcs_f4(const float* p) {
    float4 v;
    asm volatile("ld.global.cs.v4.f32 {%0,%1,%2,%3}, [%4];"
                 : "=f"(v.x), "=f"(v.y), "=f"(v.z), "=f"(v.w) : "l"(p));
    return v;
}

// ---------------------------------------------------------------------------
// Merged prep, 2 rows per warp (doubled MLP), streaming input loads:
// rows [0,C) -> normalize W row -> g_wh; rows [C,C+B) -> X row -> g_xh.
// ---------------------------------------------------------------------------
__global__ void prep_kernel(const float* __restrict__ W, const float* __restrict__ X,
                            int C, int B) {
    const int wrp  = (blockIdx.x * blockDim.x + threadIdx.x) >> 5;
    const int lane = threadIdx.x & 31;
    const int r0   = wrp * 2;
    const int r1   = r0 + 1;
    const int total = C + B;
    if (r0 >= total) return;

    const bool isx0 = r0 >= C;
    const bool isx1 = r1 >= C;
    const int  i0 = isx0 ? r0 - C : r0;
    const int  i1 = isx1 ? r1 - C : r1;
    const float* s0 = (isx0 ? X : W) + (size_t)i0 * DD;
    const float* s1 = (isx1 ? X : W) + (size_t)i1 * DD;
    const bool have1 = (r1 < total);

    // issue all 4 loads up front (MLP = 4 per thread), evict-first policy
    float4 a0 = ldcs_f4(s0 + lane * 4);
    float4 a1 = ldcs_f4(s0 + 128 + lane * 4);
    float4 b0 = have1 ? ldcs_f4(s1 + lane * 4)       : make_float4(0, 0, 0, 1);
    float4 b1 = have1 ? ldcs_f4(s1 + 128 + lane * 4) : make_float4(0, 0, 0, 1);

    float sa = a0.x*a0.x + a0.y*a0.y + a0.z*a0.z + a0.w*a0.w
             + a1.x*a1.x + a1.y*a1.y + a1.z*a1.z + a1.w*a1.w;
    float sb = b0.x*b0.x + b0.y*b0.y + b0.z*b0.z + b0.w*b0.w
             + b1.x*b1.x + b1.y*b1.y + b1.z*b1.z + b1.w*b1.w;
    #pragma unroll
    for (int o = 16; o; o >>= 1) {
        sa += __shfl_xor_sync(0xffffffffu, sa, o);
        sb += __shfl_xor_sync(0xffffffffu, sb, o);
    }
    float ia = rsqrtf(sa);
    float ib = rsqrtf(sb);
    if (lane == 0) {
        if (isx0) g_xlen[i0] = sa * ia;
        if (have1 && isx1) g_xlen[i1] = sb * ib;
    }

    {
        __half* d0 = (isx0 ? g_xh : g_wh) + (size_t)i0 * DD;
        *(__half2*)(d0 + lane * 4)           = __floats2half2_rn(a0.x * ia, a0.y * ia);
        *(__half2*)(d0 + lane * 4 + 2)       = __floats2half2_rn(a0.z * ia, a0.w * ia);
        *(__half2*)(d0 + 128 + lane * 4)     = __floats2half2_rn(a1.x * ia, a1.y * ia);
        *(__half2*)(d0 + 128 + lane * 4 + 2) = __floats2half2_rn(a1.z * ia, a1.w * ia);
    }
    if (have1) {
        __half* d1 = (isx1 ? g_xh : g_wh) + (size_t)i1 * DD;
        *(__half2*)(d1 + lane * 4)           = __floats2half2_rn(b0.x * ib, b0.y * ib);
        *(__half2*)(d1 + lane * 4 + 2)       = __floats2half2_rn(b0.z * ib, b0.w * ib);
        *(__half2*)(d1 + 128 + lane * 4)     = __floats2half2_rn(b1.x * ib, b1.y * ib);
        *(__half2*)(d1 + 128 + lane * 4 + 2) = __floats2half2_rn(b1.z * ib, b1.w * ib);
    }
}

// ---------------------------------------------------------------------------
// GEMM: CTA 128x128, 256 threads, 8 warps (2m x 4n), warp tile 64x32.
// A fully K-resident (loaded once); B 3-stage ring over K chunks of 64.
// Fragment double-buffering over ks.  Epilogue: batched loads, label fast
// path, streaming stores.   (R13/R15 champion, unchanged.)
// ---------------------------------------------------------------------------
#define BM 128
#define BN 128
#define BK 64
#define NCHUNK (DD / BK)                 // 4

#define A_OFF      0                     // 4 slabs of 16 KB = 65536
#define B_OFF      65536                 // ring 3 x 16 KB = 49152
#define SMEM_TOTAL 114688                // 112 KB -> 2 CTAs/SM

__global__ __launch_bounds__(256, 2)
void angle_mma_kernel(const int* __restrict__ Y, float* __restrict__ out, int C)
{
    extern __shared__ char smem[];
    const uint32_t sbase = smem_u32(smem);
    const int tid  = threadIdx.x;
    const int wid  = tid >> 5;
    const int lane = tid & 31;
    const int wm   = wid >> 2;     // 0..1 : warp m (64 rows)
    const int wn   = wid & 3;      // 0..3 : warp n (32 cols)

    const int bm = blockIdx.x * BM;
    const int bn = blockIdx.y * BN;

    // ---- loaders ----
    auto load_a_all = [&]() {       // 128 rows x 256 k, 4 slabs of 16 KB
        for (int i = 0; i < 16; i++) {
            int t2 = tid + i * 256;
            int chunk = t2 >> 10;
            int w3    = t2 & 1023;
            int row = w3 >> 3, blk = w3 & 7;
            uint32_t off = (uint32_t)(row * 128) + (uint32_t)((blk ^ (row & 7)) << 4);
            cp_async16(sbase + A_OFF + chunk * 16384 + off,
                       g_xh + (size_t)(bm + row) * DD + chunk * BK + blk * 8);
        }
    };
    auto load_b = [&](int buf, int kc) {          // 128 rows x 64 k
        const uint32_t bb = sbase + B_OFF + (uint32_t)buf * 16384;
        #pragma unroll
        for (int i = 0; i < 4; i++) {
            int g = tid + i * 256;
            int row = g >> 3, blk = g & 7;
            int rg = bn + row; if (rg >= C) rg = C - 1;
            uint32_t off = (uint32_t)(row * 128) + (uint32_t)((blk ^ (row & 7)) << 4);
            cp_async16(bb + off, g_wh + (size_t)rg * DD + kc + blk * 8);
        }
    };

    // ---- prologue: group0 = A + B0, group1 = B1 ----
    load_a_all();
    load_b(0, 0);
    cp_commit();
    load_b(1, BK);
    cp_commit();

    float c[4][4][4];
    #pragma unroll
    for (int mt = 0; mt < 4; mt++)
        #pragma unroll
        for (int nt = 0; nt < 4; nt++)
            #pragma unroll
            for (int q = 0; q < 4; q++) c[mt][nt][q] = 0.f;

    const int a_hi = lane >> 4;
    uint32_t a_rel[4], b_rel[2];
    #pragma unroll
    for (int mt = 0; mt < 4; mt++) {
        int r = wm * 64 + mt * 16 + (lane & 15);
        a_rel[mt] = (uint32_t)(r * 128) + (uint32_t)((r & 7) << 4);
    }
    #pragma unroll
    for (int bt = 0; bt < 2; bt++) {
        int r = wn * 32 + bt * 16 + ((lane >> 3) & 1) * 8 + (lane & 7);
        b_rel[bt] = (uint32_t)(r * 128) + (uint32_t)((r & 7) << 4);
    }

    // ---- main loop: one barrier per chunk; ks-pipelined fragments ----
    #pragma unroll
    for (int ck = 0; ck < NCHUNK; ck++) {
        if (ck == NCHUNK - 1) cp_wait<0>(); else cp_wait<1>();
        __syncthreads();                          // B[ck%3] (+A on ck=0) visible

        if (ck + 2 < NCHUNK) {                    // refill idle 3rd buffer
            load_b((ck + 2) % 3, (ck + 2) * BK);
            cp_commit();
        }

        const uint32_t ab = sbase + A_OFF + (uint32_t)ck * 16384;
        const uint32_t bb = sbase + B_OFF + (uint32_t)(ck % 3) * 16384;

        uint32_t a[2][4][4], b[2][2][4];
        const uint32_t k0 = (uint32_t)(a_hi << 4);
        #pragma unroll
        for (int mt = 0; mt < 4; mt++)
            ldsm_x4(a[0][mt][0], a[0][mt][1], a[0][mt][2], a[0][mt][3],
                    ab + (a_rel[mt] ^ k0));
        #pragma unroll
        for (int bt = 0; bt < 2; bt++)
            ldsm_x4(b[0][bt][0], b[0][bt][1], b[0][bt][2], b[0][bt][3],
                    bb + (b_rel[bt] ^ k0));

        #pragma unroll
        for (int ks = 0; ks < 4; ks++) {
            const int cur = ks & 1, nxt = cur ^ 1;
            if (ks < 3) {
                const uint32_t kc = (uint32_t)(((ks + 1) * 2 + a_hi) << 4);
                #pragma unroll
                for (int mt = 0; mt < 4; mt++)
                    ldsm_x4(a[nxt][mt][0], a[nxt][mt][1], a[nxt][mt][2], a[nxt][mt][3],
                            ab + (a_rel[mt] ^ kc));
                #pragma unroll
                for (int bt = 0; bt < 2; bt++)
                    ldsm_x4(b[nxt][bt][0], b[nxt][bt][1], b[nxt][bt][2], b[nxt][bt][3],
                            bb + (b_rel[bt] ^ kc));
            }
            #pragma unroll
            for (int mt = 0; mt < 4; mt++) {
                #pragma unroll
                for (int nt = 0; nt < 4; nt++) {
                    const int bt = nt >> 1, sub = nt & 1;
                    mma_16816(c[mt][nt][0], c[mt][nt][1], c[mt][nt][2], c[mt][nt][3],
                              a[cur][mt][0], a[cur][mt][1], a[cur][mt][2], a[cur][mt][3],
                              b[cur][bt][sub], b[cur][bt][2 + sub]);
                }
            }
        }
    }

    // ---- epilogue: batched loads, label fast path, streaming stores ----
    const float inv_pi     = 1.0f / CUDART_PI_F;
    const float inv_1plamb = 1.0f / 1001.0f;

    float xl[8]; int lab[8];
    #pragma unroll
    for (int mt = 0; mt < 4; mt++) {
        const int r0 = bm + wm * 64 + mt * 16 + (lane >> 2);
        xl[2 * mt]      = g_xlen[r0];
        xl[2 * mt + 1]  = g_xlen[r0 + 8];
        lab[2 * mt]     = Y[r0];
        lab[2 * mt + 1] = Y[r0 + 8];
    }

    #pragma unroll
    for (int mt = 0; mt < 4; mt++) {
        #pragma unroll
        for (int half = 0; half < 2; half++) {
            const int   rr  = bm + wm * 64 + mt * 16 + (lane >> 2) + half * 8;
            const float xlv = xl[2 * mt + half];
            const int   lbv = lab[2 * mt + half];
            float* rowp = out + (size_t)rr * C;
            const bool hit = ((unsigned)(lbv - bn) < (unsigned)BN);

            if (!hit) {
                #pragma unroll
                for (int nt = 0; nt < 4; nt++) {
                    const int col = bn + wn * 32 + nt * 8 + (lane & 3) * 2;
                    if (col >= C) continue;      // col even, C even -> col+1 valid
                    float v0 = c[mt][nt][half * 2 + 0];
                    float v1 = c[mt][nt][half * 2 + 1];
                    v0 = fminf(fmaxf(v0, -1.0f), 1.0f);
                    v1 = fminf(fmaxf(v1, -1.0f), 1.0f);
                    stcs_f2(rowp + col, v0 * xlv, v1 * xlv);
                }
            } else {
                #pragma unroll
                for (int nt = 0; nt < 4; nt++) {
                    const int col = bn + wn * 32 + nt * 8 + (lane & 3) * 2;
                    if (col >= C) continue;
                    float v0 = c[mt][nt][half * 2 + 0];
                    float v1 = c[mt][nt][half * 2 + 1];
                    v0 = fminf(fmaxf(v0, -1.0f), 1.0f);
                    v1 = fminf(fmaxf(v1, -1.0f), 1.0f);
                    float f0 = v0 * xlv, f1 = v1 * xlv;
                    if (col == lbv || col + 1 == lbv) {
                        const bool second = (col + 1 == lbv);
                        float cv = second ? v1 : v0;
                        float c2   = cv * cv;
                        float cosm = 8.0f * c2 * c2 - 8.0f * c2 + 1.0f;
                        float kf   = floorf(4.0f * acosf(cv) * inv_pi);
                        float sign = 1.0f - 2.0f * fmodf(kf, 2.0f);
                        float phi  = sign * cosm - 2.0f * kf;
                        float fm   = second ? f1 : f0;
                        fm += (phi * xlv - fm) * inv_1plamb;
                        if (second) f1 = fm; else f0 = fm;
                    }
                    stcs_f2(rowp + col, f0, f1);
                }
            }
        }
    }
}

// ---------------------------------------------------------------------------
// Launch
// ---------------------------------------------------------------------------
extern "C" void kernel_launch(void* const* d_in, const int* in_sizes, int n_in,
                              void* d_out, int out_size)
{
    const float* x = (const float*)d_in[0];
    const float* w = (const float*)d_in[1];
    const int*   y = (const int*)d_in[2];
    float* out     = (float*)d_out;

    const int B = in_sizes[2];            // 512
    const int D = in_sizes[0] / B;        // 256
    const int C = in_sizes[1] / D;        // 100000
    (void)D;

    static bool attr_set = false;
    if (!attr_set) {
        cudaFuncSetAttribute(angle_mma_kernel,
                             cudaFuncAttributeMaxDynamicSharedMemorySize, SMEM_TOTAL);
        attr_set = true;
    }

    {
        // 2 rows per warp
        int wpb = 8;
        int warps = (C + B + 1) / 2;
        prep_kernel<<<(warps + wpb - 1) / wpb, wpb * 32>>>(w, x, C, B);
    }

    // grid.x = m tiles (fastest -> 4 CTAs share each W n-stripe in L2)
    dim3 grid(B / BM, (C + BN - 1) / BN);
    angle_mma_kernel<<<grid, 256, SMEM_TOTAL>>>(y, out, C);
}